// round 1
// baseline (speedup 1.0000x reference)
#include <cuda_runtime.h>
#include <math.h>
#include <stddef.h>

#define BB 4
#define NN 1024
#define DD 1024
#define EE 32
#define HH 4096
#define LN_EPS 1e-5f
#define PS_EPS 1e-9f

// ---------------- scratch (device globals; no allocation allowed) ----------------
__device__ __align__(16) float g_q[EE * DD];            // normalized query [E][D]
__device__ __align__(16) float g_logits[BB * NN * EE];  // [b][n][e]
__device__ __align__(16) float g_dw[BB * NN * EE];      // dispatch weights [b][n][e]
__device__ __align__(16) float g_cw[BB * NN * EE];      // combine weights  [b][n][e]
__device__ float g_cwterm[BB * NN];
__device__ float g_cwdiag[BB * EE];
__device__ float g_dwterm[BB * EE];
__device__ __align__(16) float g_slots_part[4][BB * EE * DD];
__device__ __align__(16) float g_slots[BB * EE * DD];   // [b][e][d]
__device__ __align__(16) float g_h[EE * BB * HH];       // [e][b][h]
__device__ __align__(16) float g_eo_part[4][BB * EE * DD];
__device__ __align__(16) float g_eo[BB * EE * DD];      // [b][e][d]

// ---------------- K1: q = LayerNorm(phi*qg+qb)*scale ----------------
__global__ __launch_bounds__(256) void k_qnorm(
    const float* __restrict__ phi, const float* __restrict__ qg,
    const float* __restrict__ qb, const float* __restrict__ lng,
    const float* __restrict__ lnb, const float* __restrict__ scale_p) {
    int e = blockIdx.x;
    int t = threadIdx.x;
    __shared__ float v[DD];
    __shared__ float red[256];

    float local = 0.f;
    for (int d = t; d < DD; d += 256) {
        float x = phi[e * DD + d] * qg[d] + qb[d];
        v[d] = x;
        local += x;
    }
    red[t] = local; __syncthreads();
    for (int s = 128; s > 0; s >>= 1) { if (t < s) red[t] += red[t + s]; __syncthreads(); }
    float mean = red[0] * (1.f / DD);
    __syncthreads();

    float lv = 0.f;
    for (int d = t; d < DD; d += 256) { float c = v[d] - mean; lv += c * c; }
    red[t] = lv; __syncthreads();
    for (int s = 128; s > 0; s >>= 1) { if (t < s) red[t] += red[t + s]; __syncthreads(); }
    float var = red[0] * (1.f / DD);
    float rstd = rsqrtf(var + LN_EPS);
    float sc = *scale_p;
    for (int d = t; d < DD; d += 256)
        g_q[e * DD + d] = ((v[d] - mean) * rstd * lng[d] + lnb[d]) * sc;
}

// ---------------- K2: logits[b,n,e] = sum_d (x*kg+kb) * q[e,d] ----------------
// block: 32 rows x 32 experts, 256 threads (e = t&31, row-quad = t>>5)
__global__ __launch_bounds__(256) void k_logits(
    const float* __restrict__ x, const float* __restrict__ kg,
    const float* __restrict__ kb) {
    int b = blockIdx.y;
    int n0 = blockIdx.x * 32;
    int t = threadIdx.x;
    int e = t & 31;
    int rq = t >> 5;  // 0..7

    __shared__ float xs[32][33];
    __shared__ float qs[32][33];

    float acc0 = 0.f, acc1 = 0.f, acc2 = 0.f, acc3 = 0.f;
    int c = t & 31;
    for (int dc = 0; dc < DD; dc += 32) {
        for (int r = t >> 5; r < 32; r += 8) {
            int d = dc + c;
            xs[r][c] = x[((size_t)(b * NN) + (n0 + r)) * DD + d] * kg[d] + kb[d];
        }
        for (int r = t >> 5; r < 32; r += 8)
            qs[r][c] = g_q[r * DD + dc + c];
        __syncthreads();
#pragma unroll
        for (int k = 0; k < 32; k++) {
            float qv = qs[e][k];
            acc0 += xs[rq * 4 + 0][k] * qv;
            acc1 += xs[rq * 4 + 1][k] * qv;
            acc2 += xs[rq * 4 + 2][k] * qv;
            acc3 += xs[rq * 4 + 3][k] * qv;
        }
        __syncthreads();
    }
    g_logits[((b * NN) + (n0 + rq * 4 + 0)) * EE + e] = acc0;
    g_logits[((b * NN) + (n0 + rq * 4 + 1)) * EE + e] = acc1;
    g_logits[((b * NN) + (n0 + rq * 4 + 2)) * EE + e] = acc2;
    g_logits[((b * NN) + (n0 + rq * 4 + 3)) * EE + e] = acc3;
}

// ---------------- K3: dispatch softmax over N per (b,e) + dw metric term ----------------
__global__ __launch_bounds__(256) void k_dispatch() {
    int be = blockIdx.x;
    int b = be >> 5;
    int e = be & 31;
    int t = threadIdx.x;
    __shared__ float buf[NN];
    __shared__ float red[256];

    float m = -1e30f;
    for (int n = t; n < NN; n += 256) {
        float v = g_logits[((b * NN) + n) * EE + e];
        buf[n] = v;
        m = fmaxf(m, v);
    }
    red[t] = m; __syncthreads();
    for (int s = 128; s > 0; s >>= 1) { if (t < s) red[t] = fmaxf(red[t], red[t + s]); __syncthreads(); }
    m = red[0]; __syncthreads();

    float s = 0.f;
    for (int n = t; n < NN; n += 256) {
        float ex = expf(buf[n] - m);
        buf[n] = ex;
        s += ex;
    }
    red[t] = s; __syncthreads();
    for (int st = 128; st > 0; st >>= 1) { if (t < st) red[t] += red[t + st]; __syncthreads(); }
    float inv = 1.f / red[0]; __syncthreads();

    float ssq = 0.f, sw = 0.f;
    for (int n = t; n < NN; n += 256) {
        float w = buf[n] * inv;
        g_dw[((b * NN) + n) * EE + e] = w;
        ssq += w * w;
        sw += w;
    }
    red[t] = ssq; __syncthreads();
    for (int st = 128; st > 0; st >>= 1) { if (t < st) red[t] += red[t + st]; __syncthreads(); }
    ssq = red[0]; __syncthreads();
    red[t] = sw; __syncthreads();
    for (int st = 128; st > 0; st >>= 1) { if (t < st) red[t] += red[t + st]; __syncthreads(); }
    if (t == 0) {
        float rs = rsqrtf(ssq + PS_EPS);
        float rn = red[0] * rs;
        g_dwterm[b * EE + e] = rn * rn;
    }
}

// ---------------- K4: combine softmax over E per (b,n) + cw metric terms ----------------
__global__ __launch_bounds__(256) void k_combine() {
    int w = threadIdx.x >> 5;
    int lane = threadIdx.x & 31;
    int bn = blockIdx.x * 8 + w;

    float v = g_logits[bn * EE + lane];
    float m = v;
#pragma unroll
    for (int o = 16; o; o >>= 1) m = fmaxf(m, __shfl_xor_sync(0xffffffffu, m, o));
    float p = expf(v - m);
    float s = p;
#pragma unroll
    for (int o = 16; o; o >>= 1) s += __shfl_xor_sync(0xffffffffu, s, o);
    float cw = p / s;
    g_cw[bn * EE + lane] = cw;

    float sq = cw * cw;
#pragma unroll
    for (int o = 16; o; o >>= 1) sq += __shfl_xor_sync(0xffffffffu, sq, o);
    float scw = cw;
#pragma unroll
    for (int o = 16; o; o >>= 1) scw += __shfl_xor_sync(0xffffffffu, scw, o);

    float rs = rsqrtf(sq + PS_EPS);
    float rows = scw * rs;
    int n = bn & (NN - 1);
    int b = bn >> 10;
    float cwn = __shfl_sync(0xffffffffu, cw, n & 31);
    if (lane == 0) {
        g_cwterm[bn] = rows * rows;
        if (n < EE) g_cwdiag[b * EE + n] = (cwn * rs) * rows;
    }
}

// ---------------- K5: metric scalars ----------------
__global__ __launch_bounds__(256) void k_scalars(float* __restrict__ out) {
    __shared__ float red[256];
    int t = threadIdx.x;
    float v;

    v = 0.f; for (int i = t; i < BB * NN; i += 256) v += g_cwterm[i];
    red[t] = v; __syncthreads();
    for (int s = 128; s > 0; s >>= 1) { if (t < s) red[t] += red[t + s]; __syncthreads(); }
    float sumA = red[0]; __syncthreads();

    v = 0.f; for (int i = t; i < BB * EE; i += 256) v += g_cwdiag[i];
    red[t] = v; __syncthreads();
    for (int s = 128; s > 0; s >>= 1) { if (t < s) red[t] += red[t + s]; __syncthreads(); }
    float sumAd = red[0]; __syncthreads();

    v = 0.f; for (int i = t; i < BB * EE; i += 256) v += g_dwterm[i];
    red[t] = v; __syncthreads();
    for (int s = 128; s > 0; s >>= 1) { if (t < s) red[t] += red[t + s]; __syncthreads(); }
    float sumB = red[0]; __syncthreads();

    v = (t < BB) ? g_dwterm[t * EE] : 0.f;
    red[t] = v; __syncthreads();
    for (int s = 128; s > 0; s >>= 1) { if (t < s) red[t] += red[t + s]; __syncthreads(); }
    float sumB0 = red[0];

    if (t == 0) {
        out[(size_t)BB * NN * DD]     = (sumA - sumAd) / (float)(BB * (size_t)NN * (NN - 1));
        out[(size_t)BB * NN * DD + 1] = (sumB - sumB0) / (float)(BB * EE * (EE - 1));
    }
}

// ---------------- K6: slots partials: slots[b,e,d] = sum_n x[b,n,d]*dw[b,n,e] ----------------
// grid (dcb=16, ns=4, b=4), 256 threads: d = dcb*64 + t&63, expert-group eg = t>>6
__global__ __launch_bounds__(256) void k_slots(const float* __restrict__ x) {
    int dcb = blockIdx.x;
    int ns = blockIdx.y;
    int b = blockIdx.z;
    int t = threadIdx.x;
    int d = dcb * 64 + (t & 63);
    int eg = t >> 6;  // 0..3 (constant per warp)
    int n0 = ns * 256;

    __shared__ float dws[256][32];  // 32 KB
    for (int i = t; i < 256 * 32; i += 256)
        dws[i >> 5][i & 31] = g_dw[((b * NN) + (n0 + (i >> 5))) * EE + (i & 31)];
    __syncthreads();

    float acc[8];
#pragma unroll
    for (int i = 0; i < 8; i++) acc[i] = 0.f;

    for (int nn = 0; nn < 256; nn++) {
        float xv = x[((size_t)(b * NN) + (n0 + nn)) * DD + d];
#pragma unroll
        for (int i = 0; i < 8; i++) acc[i] += dws[nn][eg * 8 + i] * xv;
    }
#pragma unroll
    for (int i = 0; i < 8; i++) {
        int e = eg * 8 + i;
        g_slots_part[ns][((b * EE) + e) * DD + d] = acc[i];
    }
}

__global__ __launch_bounds__(256) void k_red_slots() {
    int i = blockIdx.x * 256 + threadIdx.x;  // 131072 total
    g_slots[i] = g_slots_part[0][i] + g_slots_part[1][i] +
                 g_slots_part[2][i] + g_slots_part[3][i];
}

// ---------------- K8: h[e,b,:] = gelu(slots[b,e,:] @ w1[e] + b1[e]) ----------------
// grid (jc=8, e=32), 128 threads, each thread 4 consecutive j (float4)
__global__ __launch_bounds__(128) void k_w1(
    const float* __restrict__ w1, const float* __restrict__ b1) {
    int e = blockIdx.y;
    int j0 = blockIdx.x * 512 + threadIdx.x * 4;

    __shared__ float ss[4][DD];  // 16 KB
    for (int i = threadIdx.x; i < 4 * DD; i += 128)
        ss[i >> 10][i & 1023] = g_slots[(((i >> 10) * EE) + e) * DD + (i & 1023)];
    __syncthreads();

    float4 a0 = make_float4(0.f, 0.f, 0.f, 0.f), a1 = a0, a2 = a0, a3 = a0;
    const float4* wp = reinterpret_cast<const float4*>(w1 + (size_t)e * DD * HH) + (j0 >> 2);

#pragma unroll 8
    for (int d = 0; d < DD; d++) {
        float4 wv = wp[(size_t)d * (HH / 4)];
        float s0 = ss[0][d], s1 = ss[1][d], s2 = ss[2][d], s3 = ss[3][d];
        a0.x += s0 * wv.x; a0.y += s0 * wv.y; a0.z += s0 * wv.z; a0.w += s0 * wv.w;
        a1.x += s1 * wv.x; a1.y += s1 * wv.y; a1.z += s1 * wv.z; a1.w += s1 * wv.w;
        a2.x += s2 * wv.x; a2.y += s2 * wv.y; a2.z += s2 * wv.z; a2.w += s2 * wv.w;
        a3.x += s3 * wv.x; a3.y += s3 * wv.y; a3.z += s3 * wv.z; a3.w += s3 * wv.w;
    }

    float4 bv = *reinterpret_cast<const float4*>(b1 + e * HH + j0);
    float4 accs[4] = {a0, a1, a2, a3};
#pragma unroll
    for (int b = 0; b < 4; b++) {
        float4 h4;
        float vx = accs[b].x + bv.x; h4.x = vx * normcdff(vx);
        float vy = accs[b].y + bv.y; h4.y = vy * normcdff(vy);
        float vz = accs[b].z + bv.z; h4.z = vz * normcdff(vz);
        float vw = accs[b].w + bv.w; h4.w = vw * normcdff(vw);
        *reinterpret_cast<float4*>(&g_h[(size_t)(e * 4 + b) * HH + j0]) = h4;
    }
}

// ---------------- K9: eo partials: eo[b,e,d] += h[e,b,hchunk] @ w2[e,hchunk,:] ----------------
// grid (x = dc + 2*hs -> 8, e=32), 128 threads, each thread 4 consecutive d (float4)
__global__ __launch_bounds__(128) void k_w2(const float* __restrict__ w2) {
    int e = blockIdx.y;
    int dc = blockIdx.x & 1;
    int hs = blockIdx.x >> 1;
    int d0 = dc * 512 + threadIdx.x * 4;
    int h0 = hs * 1024;

    __shared__ float hsm[4][1024];  // 16 KB
    for (int i = threadIdx.x; i < 4096; i += 128)
        hsm[i >> 10][i & 1023] = g_h[(size_t)((e * 4) + (i >> 10)) * HH + h0 + (i & 1023)];
    __syncthreads();

    float4 a0 = make_float4(0.f, 0.f, 0.f, 0.f), a1 = a0, a2 = a0, a3 = a0;
    const float4* wp = reinterpret_cast<const float4*>(
        w2 + (size_t)e * HH * DD + (size_t)h0 * DD) + (d0 >> 2);

#pragma unroll 8
    for (int hh = 0; hh < 1024; hh++) {
        float4 wv = wp[(size_t)hh * (DD / 4)];
        float h0v = hsm[0][hh], h1v = hsm[1][hh], h2v = hsm[2][hh], h3v = hsm[3][hh];
        a0.x += h0v * wv.x; a0.y += h0v * wv.y; a0.z += h0v * wv.z; a0.w += h0v * wv.w;
        a1.x += h1v * wv.x; a1.y += h1v * wv.y; a1.z += h1v * wv.z; a1.w += h1v * wv.w;
        a2.x += h2v * wv.x; a2.y += h2v * wv.y; a2.z += h2v * wv.z; a2.w += h2v * wv.w;
        a3.x += h3v * wv.x; a3.y += h3v * wv.y; a3.z += h3v * wv.z; a3.w += h3v * wv.w;
    }
    *reinterpret_cast<float4*>(&g_eo_part[hs][((0 * EE) + e) * DD + d0]) = a0;
    *reinterpret_cast<float4*>(&g_eo_part[hs][((1 * EE) + e) * DD + d0]) = a1;
    *reinterpret_cast<float4*>(&g_eo_part[hs][((2 * EE) + e) * DD + d0]) = a2;
    *reinterpret_cast<float4*>(&g_eo_part[hs][((3 * EE) + e) * DD + d0]) = a3;
}

__global__ __launch_bounds__(256) void k_red_eo(const float* __restrict__ b2) {
    int i = blockIdx.x * 256 + threadIdx.x;  // 131072 total
    int d = i & (DD - 1);
    int e = (i >> 10) & (EE - 1);
    g_eo[i] = g_eo_part[0][i] + g_eo_part[1][i] + g_eo_part[2][i] + g_eo_part[3][i] +
              b2[e * DD + d];
}

// ---------------- K10: out[b,n,d] = sum_e cw[b,n,e] * eo[b,e,d] ----------------
// grid (dc=4, nb=32, b=4), 256 threads: d = dc*256+t, 32 n rows per block
__global__ __launch_bounds__(256) void k_out(float* __restrict__ out) {
    int b = blockIdx.z;
    int n0 = blockIdx.y * 32;
    int d = blockIdx.x * 256 + threadIdx.x;

    __shared__ float cws[32][EE];
    for (int i = threadIdx.x; i < 32 * EE; i += 256)
        cws[i >> 5][i & 31] = g_cw[((b * NN) + (n0 + (i >> 5))) * EE + (i & 31)];
    __syncthreads();

    float acc[32];
#pragma unroll
    for (int i = 0; i < 32; i++) acc[i] = 0.f;

#pragma unroll 4
    for (int e = 0; e < EE; e++) {
        float ev = g_eo[((b * EE) + e) * DD + d];
#pragma unroll
        for (int i = 0; i < 32; i++) acc[i] += cws[i][e] * ev;
    }
#pragma unroll
    for (int i = 0; i < 32; i++)
        out[((size_t)(b * NN) + (n0 + i)) * DD + d] = acc[i];
}

// ---------------- launch ----------------
extern "C" void kernel_launch(void* const* d_in, const int* in_sizes, int n_in,
                              void* d_out, int out_size) {
    const float* x   = (const float*)d_in[0];
    const float* phi = (const float*)d_in[1];
    const float* kg  = (const float*)d_in[2];
    const float* kb  = (const float*)d_in[3];
    const float* qg  = (const float*)d_in[4];
    const float* qb  = (const float*)d_in[5];
    const float* lg  = (const float*)d_in[6];
    const float* lb  = (const float*)d_in[7];
    const float* sc  = (const float*)d_in[8];
    const float* w1  = (const float*)d_in[9];
    const float* b1  = (const float*)d_in[10];
    const float* w2  = (const float*)d_in[11];
    const float* b2  = (const float*)d_in[12];
    float* out = (float*)d_out;

    k_qnorm<<<EE, 256>>>(phi, qg, qb, lg, lb, sc);
    k_logits<<<dim3(32, 4), 256>>>(x, kg, kb);
    k_dispatch<<<128, 256>>>();
    k_combine<<<512, 256>>>();
    k_scalars<<<1, 256>>>(out);
    k_slots<<<dim3(16, 4, 4), 256>>>(x);
    k_red_slots<<<512, 256>>>();
    k_w1<<<dim3(8, 32), 128>>>(w1, b1);
    k_w2<<<dim3(8, 32), 128>>>(w2);
    k_red_eo<<<512, 256>>>(b2);
    k_out<<<dim3(4, 32, 4), 256>>>(out);
}

// round 2
// speedup vs baseline: 1.3825x; 1.3825x over previous
#include <cuda_runtime.h>
#include <math.h>
#include <stddef.h>

#define BB 4
#define NN 1024
#define DD 1024
#define EE 32
#define HH 4096
#define LN_EPS 1e-5f
#define PS_EPS 1e-9f

// ---------------- scratch (device globals; no allocation allowed) ----------------
__device__ __align__(16) float g_q[EE * DD];            // normalized query [E][D]
__device__ __align__(16) float g_logits[BB * NN * EE];  // [b][n][e]
__device__ __align__(16) float g_dw[BB * NN * EE];      // dispatch weights [b][n][e]
__device__ __align__(16) float g_cw[BB * NN * EE];      // combine weights  [b][n][e]
__device__ float g_cwterm[BB * NN];
__device__ float g_cwdiag[BB * EE];
__device__ float g_dwterm[BB * EE];
__device__ __align__(16) float g_slots_part[4][BB * EE * DD];
__device__ __align__(16) float g_h1p[2][EE * BB * HH];  // pre-gelu partials (k-split 2)
__device__ __align__(16) float g_h[EE * BB * HH];       // [e][b][h]
__device__ __align__(16) float g_eo_part[8][BB * EE * DD];
__device__ __align__(16) float g_eo[BB * EE * DD];      // [b][e][d]

// ---------------- K1: q = LayerNorm(phi*qg+qb)*scale ----------------
__global__ __launch_bounds__(256) void k_qnorm(
    const float* __restrict__ phi, const float* __restrict__ qg,
    const float* __restrict__ qb, const float* __restrict__ lng,
    const float* __restrict__ lnb, const float* __restrict__ scale_p) {
    int e = blockIdx.x;
    int t = threadIdx.x;
    __shared__ float v[DD];
    __shared__ float red[256];

    float local = 0.f;
    for (int d = t; d < DD; d += 256) {
        float x = phi[e * DD + d] * qg[d] + qb[d];
        v[d] = x;
        local += x;
    }
    red[t] = local; __syncthreads();
    for (int s = 128; s > 0; s >>= 1) { if (t < s) red[t] += red[t + s]; __syncthreads(); }
    float mean = red[0] * (1.f / DD);
    __syncthreads();

    float lv = 0.f;
    for (int d = t; d < DD; d += 256) { float c = v[d] - mean; lv += c * c; }
    red[t] = lv; __syncthreads();
    for (int s = 128; s > 0; s >>= 1) { if (t < s) red[t] += red[t + s]; __syncthreads(); }
    float var = red[0] * (1.f / DD);
    float rstd = rsqrtf(var + LN_EPS);
    float sc = *scale_p;
    for (int d = t; d < DD; d += 256)
        g_q[e * DD + d] = ((v[d] - mean) * rstd * lng[d] + lnb[d]) * sc;
}

// ---------------- K2: logits[b,n,e] = sum_d (x*kg+kb) * q[e,d] ----------------
__global__ __launch_bounds__(256) void k_logits(
    const float* __restrict__ x, const float* __restrict__ kg,
    const float* __restrict__ kb) {
    int b = blockIdx.y;
    int n0 = blockIdx.x * 32;
    int t = threadIdx.x;
    int e = t & 31;
    int rq = t >> 5;  // 0..7

    __shared__ float xs[32][33];
    __shared__ float qs[32][33];

    float acc0 = 0.f, acc1 = 0.f, acc2 = 0.f, acc3 = 0.f;
    int c = t & 31;
    for (int dc = 0; dc < DD; dc += 32) {
        for (int r = t >> 5; r < 32; r += 8) {
            int d = dc + c;
            xs[r][c] = x[((size_t)(b * NN) + (n0 + r)) * DD + d] * kg[d] + kb[d];
        }
        for (int r = t >> 5; r < 32; r += 8)
            qs[r][c] = g_q[r * DD + dc + c];
        __syncthreads();
#pragma unroll
        for (int k = 0; k < 32; k++) {
            float qv = qs[e][k];
            acc0 += xs[rq * 4 + 0][k] * qv;
            acc1 += xs[rq * 4 + 1][k] * qv;
            acc2 += xs[rq * 4 + 2][k] * qv;
            acc3 += xs[rq * 4 + 3][k] * qv;
        }
        __syncthreads();
    }
    g_logits[((b * NN) + (n0 + rq * 4 + 0)) * EE + e] = acc0;
    g_logits[((b * NN) + (n0 + rq * 4 + 1)) * EE + e] = acc1;
    g_logits[((b * NN) + (n0 + rq * 4 + 2)) * EE + e] = acc2;
    g_logits[((b * NN) + (n0 + rq * 4 + 3)) * EE + e] = acc3;
}

// ---------------- K3: dispatch softmax over N per (b,e) + dw metric term ----------------
__global__ __launch_bounds__(256) void k_dispatch() {
    int be = blockIdx.x;
    int b = be >> 5;
    int e = be & 31;
    int t = threadIdx.x;
    __shared__ float buf[NN];
    __shared__ float red[256];

    float m = -1e30f;
    for (int n = t; n < NN; n += 256) {
        float v = g_logits[((b * NN) + n) * EE + e];
        buf[n] = v;
        m = fmaxf(m, v);
    }
    red[t] = m; __syncthreads();
    for (int s = 128; s > 0; s >>= 1) { if (t < s) red[t] = fmaxf(red[t], red[t + s]); __syncthreads(); }
    m = red[0]; __syncthreads();

    float s = 0.f;
    for (int n = t; n < NN; n += 256) {
        float ex = expf(buf[n] - m);
        buf[n] = ex;
        s += ex;
    }
    red[t] = s; __syncthreads();
    for (int st = 128; st > 0; st >>= 1) { if (t < st) red[t] += red[t + st]; __syncthreads(); }
    float inv = 1.f / red[0]; __syncthreads();

    float ssq = 0.f, sw = 0.f;
    for (int n = t; n < NN; n += 256) {
        float w = buf[n] * inv;
        g_dw[((b * NN) + n) * EE + e] = w;
        ssq += w * w;
        sw += w;
    }
    red[t] = ssq; __syncthreads();
    for (int st = 128; st > 0; st >>= 1) { if (t < st) red[t] += red[t + st]; __syncthreads(); }
    ssq = red[0]; __syncthreads();
    red[t] = sw; __syncthreads();
    for (int st = 128; st > 0; st >>= 1) { if (t < st) red[t] += red[t + st]; __syncthreads(); }
    if (t == 0) {
        float rs = rsqrtf(ssq + PS_EPS);
        float rn = red[0] * rs;
        g_dwterm[b * EE + e] = rn * rn;
    }
}

// ---------------- K4: combine softmax over E per (b,n) + cw metric terms ----------------
__global__ __launch_bounds__(256) void k_combine() {
    int w = threadIdx.x >> 5;
    int lane = threadIdx.x & 31;
    int bn = blockIdx.x * 8 + w;

    float v = g_logits[bn * EE + lane];
    float m = v;
#pragma unroll
    for (int o = 16; o; o >>= 1) m = fmaxf(m, __shfl_xor_sync(0xffffffffu, m, o));
    float p = expf(v - m);
    float s = p;
#pragma unroll
    for (int o = 16; o; o >>= 1) s += __shfl_xor_sync(0xffffffffu, s, o);
    float cw = p / s;
    g_cw[bn * EE + lane] = cw;

    float sq = cw * cw;
#pragma unroll
    for (int o = 16; o; o >>= 1) sq += __shfl_xor_sync(0xffffffffu, sq, o);
    float scw = cw;
#pragma unroll
    for (int o = 16; o; o >>= 1) scw += __shfl_xor_sync(0xffffffffu, scw, o);

    float rs = rsqrtf(sq + PS_EPS);
    float rows = scw * rs;
    int n = bn & (NN - 1);
    int b = bn >> 10;
    float cwn = __shfl_sync(0xffffffffu, cw, n & 31);
    if (lane == 0) {
        g_cwterm[bn] = rows * rows;
        if (n < EE) g_cwdiag[b * EE + n] = (cwn * rs) * rows;
    }
}

// ---------------- K5: metric scalars ----------------
__global__ __launch_bounds__(256) void k_scalars(float* __restrict__ out) {
    __shared__ float red[256];
    int t = threadIdx.x;
    float v;

    v = 0.f; for (int i = t; i < BB * NN; i += 256) v += g_cwterm[i];
    red[t] = v; __syncthreads();
    for (int s = 128; s > 0; s >>= 1) { if (t < s) red[t] += red[t + s]; __syncthreads(); }
    float sumA = red[0]; __syncthreads();

    v = 0.f; for (int i = t; i < BB * EE; i += 256) v += g_cwdiag[i];
    red[t] = v; __syncthreads();
    for (int s = 128; s > 0; s >>= 1) { if (t < s) red[t] += red[t + s]; __syncthreads(); }
    float sumAd = red[0]; __syncthreads();

    v = 0.f; for (int i = t; i < BB * EE; i += 256) v += g_dwterm[i];
    red[t] = v; __syncthreads();
    for (int s = 128; s > 0; s >>= 1) { if (t < s) red[t] += red[t + s]; __syncthreads(); }
    float sumB = red[0]; __syncthreads();

    v = (t < BB) ? g_dwterm[t * EE] : 0.f;
    red[t] = v; __syncthreads();
    for (int s = 128; s > 0; s >>= 1) { if (t < s) red[t] += red[t + s]; __syncthreads(); }
    float sumB0 = red[0];

    if (t == 0) {
        out[(size_t)BB * NN * DD]     = (sumA - sumAd) / (float)(BB * (size_t)NN * (NN - 1));
        out[(size_t)BB * NN * DD + 1] = (sumB - sumB0) / (float)(BB * EE * (EE - 1));
    }
}

// ---------------- K6: slots partials: slots[b,e,d] = sum_n x[b,n,d]*dw[b,n,e] ----------------
__global__ __launch_bounds__(256) void k_slots(const float* __restrict__ x) {
    int dcb = blockIdx.x;
    int ns = blockIdx.y;
    int b = blockIdx.z;
    int t = threadIdx.x;
    int d = dcb * 64 + (t & 63);
    int eg = t >> 6;  // 0..3
    int n0 = ns * 256;

    __shared__ float dws[256][32];  // 32 KB
    for (int i = t; i < 256 * 32; i += 256)
        dws[i >> 5][i & 31] = g_dw[((b * NN) + (n0 + (i >> 5))) * EE + (i & 31)];
    __syncthreads();

    float acc[8];
#pragma unroll
    for (int i = 0; i < 8; i++) acc[i] = 0.f;

    for (int nn = 0; nn < 256; nn++) {
        float xv = x[((size_t)(b * NN) + (n0 + nn)) * DD + d];
#pragma unroll
        for (int i = 0; i < 8; i++) acc[i] += dws[nn][eg * 8 + i] * xv;
    }
#pragma unroll
    for (int i = 0; i < 8; i++) {
        int e = eg * 8 + i;
        g_slots_part[ns][((b * EE) + e) * DD + d] = acc[i];
    }
}

// ---------------- K7: w1 pass (k-split 2, slot-partial reduction fused in) ----------------
// grid (jc=8, ks=2, e=32) = 512 blocks, 128 threads, each thread 4 consecutive j
__global__ __launch_bounds__(128) void k_w1(const float* __restrict__ w1) {
    int e = blockIdx.z;
    int ks = blockIdx.y;
    int j0 = blockIdx.x * 512 + threadIdx.x * 4;
    int d0 = ks * 512;

    __shared__ float ss[4][512];  // 8 KB: slots[b][d0:d0+512] for this expert
    for (int i = threadIdx.x; i < 4 * 512; i += 128) {
        int b = i >> 9;
        int d = (i & 511) + d0;
        size_t idx = (size_t)((b * EE) + e) * DD + d;
        ss[b][i & 511] = g_slots_part[0][idx] + g_slots_part[1][idx] +
                         g_slots_part[2][idx] + g_slots_part[3][idx];
    }
    __syncthreads();

    float4 a0 = make_float4(0.f, 0.f, 0.f, 0.f), a1 = a0, a2 = a0, a3 = a0;
    const float4* wp = reinterpret_cast<const float4*>(w1 + (size_t)e * DD * HH +
                                                       (size_t)d0 * HH) + (j0 >> 2);

#pragma unroll 8
    for (int d = 0; d < 512; d++) {
        float4 wv = __ldcs(wp + (size_t)d * (HH / 4));
        float s0 = ss[0][d], s1 = ss[1][d], s2 = ss[2][d], s3 = ss[3][d];
        a0.x += s0 * wv.x; a0.y += s0 * wv.y; a0.z += s0 * wv.z; a0.w += s0 * wv.w;
        a1.x += s1 * wv.x; a1.y += s1 * wv.y; a1.z += s1 * wv.z; a1.w += s1 * wv.w;
        a2.x += s2 * wv.x; a2.y += s2 * wv.y; a2.z += s2 * wv.z; a2.w += s2 * wv.w;
        a3.x += s3 * wv.x; a3.y += s3 * wv.y; a3.z += s3 * wv.z; a3.w += s3 * wv.w;
    }
    *reinterpret_cast<float4*>(&g_h1p[ks][(size_t)(e * 4 + 0) * HH + j0]) = a0;
    *reinterpret_cast<float4*>(&g_h1p[ks][(size_t)(e * 4 + 1) * HH + j0]) = a1;
    *reinterpret_cast<float4*>(&g_h1p[ks][(size_t)(e * 4 + 2) * HH + j0]) = a2;
    *reinterpret_cast<float4*>(&g_h1p[ks][(size_t)(e * 4 + 3) * HH + j0]) = a3;
}

// ---------------- K8: gelu(sum of k-split partials + b1) ----------------
__global__ __launch_bounds__(256) void k_gelu(const float* __restrict__ b1) {
    int i = blockIdx.x * 256 + threadIdx.x;  // EE*BB*HH = 524288
    int j = i & (HH - 1);
    int e = i >> 14;  // (e*4+b)*HH layout: e = i / (4*HH)
    float v = g_h1p[0][i] + g_h1p[1][i] + b1[e * HH + j];
    g_h[i] = v * normcdff(v);
}

// ---------------- K9: w2 pass (h-split 8) ----------------
// grid (x = dc(2) x hs(8) = 16, e=32) = 512 blocks, 128 threads, 4 d per thread
__global__ __launch_bounds__(128) void k_w2(const float* __restrict__ w2) {
    int e = blockIdx.y;
    int dc = blockIdx.x & 1;
    int hs = blockIdx.x >> 1;
    int d0 = dc * 512 + threadIdx.x * 4;
    int h0 = hs * 512;

    __shared__ float hsm[4][512];  // 8 KB
    for (int i = threadIdx.x; i < 4 * 512; i += 128)
        hsm[i >> 9][i & 511] = g_h[(size_t)((e * 4) + (i >> 9)) * HH + h0 + (i & 511)];
    __syncthreads();

    float4 a0 = make_float4(0.f, 0.f, 0.f, 0.f), a1 = a0, a2 = a0, a3 = a0;
    const float4* wp = reinterpret_cast<const float4*>(
        w2 + (size_t)e * HH * DD + (size_t)h0 * DD) + (d0 >> 2);

#pragma unroll 8
    for (int hh = 0; hh < 512; hh++) {
        float4 wv = __ldcs(wp + (size_t)hh * (DD / 4));
        float h0v = hsm[0][hh], h1v = hsm[1][hh], h2v = hsm[2][hh], h3v = hsm[3][hh];
        a0.x += h0v * wv.x; a0.y += h0v * wv.y; a0.z += h0v * wv.z; a0.w += h0v * wv.w;
        a1.x += h1v * wv.x; a1.y += h1v * wv.y; a1.z += h1v * wv.z; a1.w += h1v * wv.w;
        a2.x += h2v * wv.x; a2.y += h2v * wv.y; a2.z += h2v * wv.z; a2.w += h2v * wv.w;
        a3.x += h3v * wv.x; a3.y += h3v * wv.y; a3.z += h3v * wv.z; a3.w += h3v * wv.w;
    }
    *reinterpret_cast<float4*>(&g_eo_part[hs][((0 * EE) + e) * DD + d0]) = a0;
    *reinterpret_cast<float4*>(&g_eo_part[hs][((1 * EE) + e) * DD + d0]) = a1;
    *reinterpret_cast<float4*>(&g_eo_part[hs][((2 * EE) + e) * DD + d0]) = a2;
    *reinterpret_cast<float4*>(&g_eo_part[hs][((3 * EE) + e) * DD + d0]) = a3;
}

__global__ __launch_bounds__(256) void k_red_eo(const float* __restrict__ b2) {
    int i = blockIdx.x * 256 + threadIdx.x;  // 131072 total
    int d = i & (DD - 1);
    int e = (i >> 10) & (EE - 1);
    float s = b2[e * DD + d];
#pragma unroll
    for (int p = 0; p < 8; p++) s += g_eo_part[p][i];
    g_eo[i] = s;
}

// ---------------- K10: out[b,n,d] = sum_e cw[b,n,e] * eo[b,e,d] ----------------
__global__ __launch_bounds__(256) void k_out(float* __restrict__ out) {
    int b = blockIdx.z;
    int n0 = blockIdx.y * 32;
    int d = blockIdx.x * 256 + threadIdx.x;

    __shared__ float cws[32][EE];
    for (int i = threadIdx.x; i < 32 * EE; i += 256)
        cws[i >> 5][i & 31] = g_cw[((b * NN) + (n0 + (i >> 5))) * EE + (i & 31)];
    __syncthreads();

    float acc[32];
#pragma unroll
    for (int i = 0; i < 32; i++) acc[i] = 0.f;

#pragma unroll 4
    for (int e = 0; e < EE; e++) {
        float ev = g_eo[((b * EE) + e) * DD + d];
#pragma unroll
        for (int i = 0; i < 32; i++) acc[i] += cws[i][e] * ev;
    }
#pragma unroll
    for (int i = 0; i < 32; i++)
        out[((size_t)(b * NN) + (n0 + i)) * DD + d] = acc[i];
}

// ---------------- launch ----------------
extern "C" void kernel_launch(void* const* d_in, const int* in_sizes, int n_in,
                              void* d_out, int out_size) {
    const float* x   = (const float*)d_in[0];
    const float* phi = (const float*)d_in[1];
    const float* kg  = (const float*)d_in[2];
    const float* kb  = (const float*)d_in[3];
    const float* qg  = (const float*)d_in[4];
    const float* qb  = (const float*)d_in[5];
    const float* lg  = (const float*)d_in[6];
    const float* lb  = (const float*)d_in[7];
    const float* sc  = (const float*)d_in[8];
    const float* w1  = (const float*)d_in[9];
    const float* b1  = (const float*)d_in[10];
    const float* w2  = (const float*)d_in[11];
    const float* b2  = (const float*)d_in[12];
    float* out = (float*)d_out;

    k_qnorm<<<EE, 256>>>(phi, qg, qb, lg, lb, sc);
    k_logits<<<dim3(32, 4), 256>>>(x, kg, kb);
    k_dispatch<<<128, 256>>>();
    k_combine<<<512, 256>>>();
    k_scalars<<<1, 256>>>(out);
    k_slots<<<dim3(16, 4, 4), 256>>>(x);
    k_w1<<<dim3(8, 2, 32), 128>>>(w1);
    k_gelu<<<2048, 256>>>(b1);
    k_w2<<<dim3(16, 32), 128>>>(w2);
    k_red_eo<<<512, 256>>>(b2);
    k_out<<<dim3(4, 32, 4), 256>>>(out);
}

// round 3
// speedup vs baseline: 1.7926x; 1.2966x over previous
#include <cuda_runtime.h>
#include <math.h>
#include <stddef.h>

#define BB 4
#define NN 1024
#define DD 1024
#define EE 32
#define HH 4096
#define LN_EPS 1e-5f
#define PS_EPS 1e-9f

// ---------------- scratch (device globals) ----------------
__device__ __align__(16) float g_q[EE * DD];
__device__ __align__(16) float g_logits[BB * NN * EE];    // [b][n][e]
__device__ __align__(16) float g_logitsT[BB * EE * NN];   // [b][e][n]
__device__ __align__(16) float g_cw[BB * NN * EE];
__device__ __align__(16) float2 g_minv[BB * EE];          // (max, 1/sum) per (b,e)
__device__ float g_cwterm[BB * NN];
__device__ float g_cwdiag[BB * EE];
__device__ float g_dwterm[BB * EE];
__device__ __align__(16) float g_slots_part[4][BB * EE * DD];
__device__ __align__(16) float g_h1p[4][EE * BB * HH];    // pre-gelu partials (k-split 4)
__device__ __align__(16) float g_eo_part[16][BB * EE * DD];
__device__ __align__(16) float g_eo[BB * EE * DD];

// ---------------- K1: q = LayerNorm(phi*qg+qb)*scale ----------------
__global__ __launch_bounds__(256) void k_qnorm(
    const float* __restrict__ phi, const float* __restrict__ qg,
    const float* __restrict__ qb, const float* __restrict__ lng,
    const float* __restrict__ lnb, const float* __restrict__ scale_p) {
    int e = blockIdx.x;
    int t = threadIdx.x;
    __shared__ float v[DD];
    __shared__ float red[256];

    float local = 0.f;
    for (int d = t; d < DD; d += 256) {
        float x = phi[e * DD + d] * qg[d] + qb[d];
        v[d] = x;
        local += x;
    }
    red[t] = local; __syncthreads();
    for (int s = 128; s > 0; s >>= 1) { if (t < s) red[t] += red[t + s]; __syncthreads(); }
    float mean = red[0] * (1.f / DD);
    __syncthreads();

    float lv = 0.f;
    for (int d = t; d < DD; d += 256) { float c = v[d] - mean; lv += c * c; }
    red[t] = lv; __syncthreads();
    for (int s = 128; s > 0; s >>= 1) { if (t < s) red[t] += red[t + s]; __syncthreads(); }
    float var = red[0] * (1.f / DD);
    float rstd = rsqrtf(var + LN_EPS);
    float sc = *scale_p;
    for (int d = t; d < DD; d += 256)
        g_q[e * DD + d] = ((v[d] - mean) * rstd * lng[d] + lnb[d]) * sc;
}

// ---------------- K2: logits (writes both layouts) ----------------
__global__ __launch_bounds__(256) void k_logits(
    const float* __restrict__ x, const float* __restrict__ kg,
    const float* __restrict__ kb) {
    int b = blockIdx.y;
    int n0 = blockIdx.x * 32;
    int t = threadIdx.x;
    int e = t & 31;
    int rq = t >> 5;  // 0..7

    __shared__ float xs[32][33];
    __shared__ float qs[32][33];

    float acc0 = 0.f, acc1 = 0.f, acc2 = 0.f, acc3 = 0.f;
    int c = t & 31;
    for (int dc = 0; dc < DD; dc += 32) {
        for (int r = t >> 5; r < 32; r += 8) {
            int d = dc + c;
            xs[r][c] = x[((size_t)(b * NN) + (n0 + r)) * DD + d] * kg[d] + kb[d];
        }
        for (int r = t >> 5; r < 32; r += 8)
            qs[r][c] = g_q[r * DD + dc + c];
        __syncthreads();
#pragma unroll
        for (int k = 0; k < 32; k++) {
            float qv = qs[e][k];
            acc0 += xs[rq * 4 + 0][k] * qv;
            acc1 += xs[rq * 4 + 1][k] * qv;
            acc2 += xs[rq * 4 + 2][k] * qv;
            acc3 += xs[rq * 4 + 3][k] * qv;
        }
        __syncthreads();
    }
#pragma unroll
    for (int r = 0; r < 4; r++) {
        float a = (r == 0) ? acc0 : (r == 1) ? acc1 : (r == 2) ? acc2 : acc3;
        int n = n0 + rq * 4 + r;
        g_logits[((b * NN) + n) * EE + e] = a;
        g_logitsT[((size_t)(b * EE) + e) * NN + n] = a;
    }
}

// ---------------- K3: dispatch softmax stats per (b,e) + dw metric ----------------
__global__ __launch_bounds__(256) void k_dstats() {
    int be = blockIdx.x;
    int t = threadIdx.x;
    __shared__ float red[256];

    const float4* L = reinterpret_cast<const float4*>(g_logitsT + (size_t)be * NN);
    float4 v = L[t];

    float m = fmaxf(fmaxf(v.x, v.y), fmaxf(v.z, v.w));
    red[t] = m; __syncthreads();
    for (int s = 128; s > 0; s >>= 1) { if (t < s) red[t] = fmaxf(red[t], red[t + s]); __syncthreads(); }
    m = red[0]; __syncthreads();

    float ex0 = expf(v.x - m), ex1 = expf(v.y - m), ex2 = expf(v.z - m), ex3 = expf(v.w - m);
    red[t] = ex0 + ex1 + ex2 + ex3; __syncthreads();
    for (int s = 128; s > 0; s >>= 1) { if (t < s) red[t] += red[t + s]; __syncthreads(); }
    float ssum = red[0]; __syncthreads();

    red[t] = ex0 * ex0 + ex1 * ex1 + ex2 * ex2 + ex3 * ex3; __syncthreads();
    for (int s = 128; s > 0; s >>= 1) { if (t < s) red[t] += red[t + s]; __syncthreads(); }

    if (t == 0) {
        float ssq = red[0];
        float inv = 1.f / ssum;
        g_minv[be] = make_float2(m, inv);
        float wsq = ssq * inv * inv;           // sum of w^2
        float rs = rsqrtf(wsq + PS_EPS);
        float rn = (ssum * inv) * rs;          // rowsum of normalized w
        g_dwterm[be] = rn * rn;
    }
}

// ---------------- K4: slots partials (dispatch weights computed on the fly) ----------------
__global__ __launch_bounds__(256) void k_slots(const float* __restrict__ x) {
    int dcb = blockIdx.x;
    int ns = blockIdx.y;
    int b = blockIdx.z;
    int t = threadIdx.x;
    int d = dcb * 64 + (t & 63);
    int eg = t >> 6;  // 0..3
    int n0 = ns * 256;

    __shared__ float dws[256][33];  // ~34 KB
    __shared__ float2 minv[EE];
    if (t < EE) minv[t] = g_minv[b * EE + t];
    __syncthreads();
    for (int i = t; i < EE * 256; i += 256) {
        int e = i >> 8, nn = i & 255;
        float lv = g_logitsT[((size_t)(b * EE) + e) * NN + n0 + nn];
        dws[nn][e] = expf(lv - minv[e].x) * minv[e].y;
    }
    __syncthreads();

    float acc[8];
#pragma unroll
    for (int i = 0; i < 8; i++) acc[i] = 0.f;

#pragma unroll 4
    for (int nn = 0; nn < 256; nn++) {
        float xv = x[((size_t)(b * NN) + (n0 + nn)) * DD + d];
#pragma unroll
        for (int i = 0; i < 8; i++) acc[i] += dws[nn][eg * 8 + i] * xv;
    }
#pragma unroll
    for (int i = 0; i < 8; i++) {
        int e = eg * 8 + i;
        g_slots_part[ns][((b * EE) + e) * DD + d] = acc[i];
    }
}

// ---------------- K5: w1 pass (k-split 4, slot reduction fused) ----------------
// grid (jc=8, ks=4, e=32) = 1024 blocks, 128 threads
__global__ __launch_bounds__(128) void k_w1(const float* __restrict__ w1) {
    int e = blockIdx.z;
    int ks = blockIdx.y;
    int j0 = blockIdx.x * 512 + threadIdx.x * 4;
    int d0 = ks * 256;

    __shared__ float4 ss4[256];  // [d] -> (b0,b1,b2,b3)
    for (int i = threadIdx.x; i < 4 * 256; i += 128) {
        int b = i >> 8, d = i & 255;
        size_t idx = (size_t)((b * EE) + e) * DD + d0 + d;
        float v = g_slots_part[0][idx] + g_slots_part[1][idx] +
                  g_slots_part[2][idx] + g_slots_part[3][idx];
        reinterpret_cast<float*>(ss4)[d * 4 + b] = v;
    }
    __syncthreads();

    float4 a0 = make_float4(0.f, 0.f, 0.f, 0.f), a1 = a0, a2 = a0, a3 = a0;
    const float4* wp = reinterpret_cast<const float4*>(w1 + (size_t)e * DD * HH +
                                                      (size_t)d0 * HH) + (j0 >> 2);
#pragma unroll 8
    for (int d = 0; d < 256; d++) {
        float4 wv = __ldcs(wp);
        wp += (HH / 4);
        float4 sv = ss4[d];
        a0.x += sv.x * wv.x; a0.y += sv.x * wv.y; a0.z += sv.x * wv.z; a0.w += sv.x * wv.w;
        a1.x += sv.y * wv.x; a1.y += sv.y * wv.y; a1.z += sv.y * wv.z; a1.w += sv.y * wv.w;
        a2.x += sv.z * wv.x; a2.y += sv.z * wv.y; a2.z += sv.z * wv.z; a2.w += sv.z * wv.w;
        a3.x += sv.w * wv.x; a3.y += sv.w * wv.y; a3.z += sv.w * wv.z; a3.w += sv.w * wv.w;
    }
    *reinterpret_cast<float4*>(&g_h1p[ks][(size_t)(e * 4 + 0) * HH + j0]) = a0;
    *reinterpret_cast<float4*>(&g_h1p[ks][(size_t)(e * 4 + 1) * HH + j0]) = a1;
    *reinterpret_cast<float4*>(&g_h1p[ks][(size_t)(e * 4 + 2) * HH + j0]) = a2;
    *reinterpret_cast<float4*>(&g_h1p[ks][(size_t)(e * 4 + 3) * HH + j0]) = a3;
}

// ---------------- K6: combine softmax (64 rows/block) + cw metric terms ----------------
__global__ __launch_bounds__(256) void k_combine() {
    int t = threadIdx.x;
    int w = t >> 5, l = t & 31;
    int bn0 = blockIdx.x * 64;
    __shared__ float cs[64][33];

#pragma unroll
    for (int k = 0; k < 2; k++) {
        int f = t + k * 256;       // float4 id 0..511
        int row = f >> 3, q = f & 7;
        float4 v = *reinterpret_cast<const float4*>(&g_logits[(bn0 + row) * EE + q * 4]);
        cs[row][q * 4 + 0] = v.x; cs[row][q * 4 + 1] = v.y;
        cs[row][q * 4 + 2] = v.z; cs[row][q * 4 + 3] = v.w;
    }
    __syncthreads();

    int r = w * 8 + (l >> 2);      // local row
    int j = l & 3;                 // quad id
    float v[8];
#pragma unroll
    for (int i = 0; i < 8; i++) v[i] = cs[r][j * 8 + i];

    float m = v[0];
#pragma unroll
    for (int i = 1; i < 8; i++) m = fmaxf(m, v[i]);
    m = fmaxf(m, __shfl_xor_sync(0xffffffffu, m, 1));
    m = fmaxf(m, __shfl_xor_sync(0xffffffffu, m, 2));

    float ex[8], s = 0.f;
#pragma unroll
    for (int i = 0; i < 8; i++) { ex[i] = expf(v[i] - m); s += ex[i]; }
    s += __shfl_xor_sync(0xffffffffu, s, 1);
    s += __shfl_xor_sync(0xffffffffu, s, 2);
    float inv = 1.f / s;

    float cw[8], sq = 0.f, sc = 0.f;
#pragma unroll
    for (int i = 0; i < 8; i++) { cw[i] = ex[i] * inv; sq += cw[i] * cw[i]; sc += cw[i]; }
    sq += __shfl_xor_sync(0xffffffffu, sq, 1);
    sq += __shfl_xor_sync(0xffffffffu, sq, 2);
    sc += __shfl_xor_sync(0xffffffffu, sc, 1);
    sc += __shfl_xor_sync(0xffffffffu, sc, 2);

    int bn = bn0 + r;
    *reinterpret_cast<float4*>(&g_cw[bn * EE + j * 8]) =
        make_float4(cw[0], cw[1], cw[2], cw[3]);
    *reinterpret_cast<float4*>(&g_cw[bn * EE + j * 8 + 4]) =
        make_float4(cw[4], cw[5], cw[6], cw[7]);

    float rs = rsqrtf(sq + PS_EPS);
    float rows = sc * rs;
    if (j == 0) g_cwterm[bn] = rows * rows;
    int n = bn & (NN - 1);
    int b = bn >> 10;
    if (n < EE && j == (n >> 3))
        g_cwdiag[b * EE + n] = cw[n & 7] * rs * rows;
}

// ---------------- K7: metric scalars ----------------
__global__ __launch_bounds__(256) void k_scalars(float* __restrict__ out) {
    __shared__ float red[256];
    int t = threadIdx.x;
    float v;

    v = 0.f; for (int i = t; i < BB * NN; i += 256) v += g_cwterm[i];
    red[t] = v; __syncthreads();
    for (int s = 128; s > 0; s >>= 1) { if (t < s) red[t] += red[t + s]; __syncthreads(); }
    float sumA = red[0]; __syncthreads();

    v = 0.f; for (int i = t; i < BB * EE; i += 256) v += g_cwdiag[i];
    red[t] = v; __syncthreads();
    for (int s = 128; s > 0; s >>= 1) { if (t < s) red[t] += red[t + s]; __syncthreads(); }
    float sumAd = red[0]; __syncthreads();

    v = 0.f; for (int i = t; i < BB * EE; i += 256) v += g_dwterm[i];
    red[t] = v; __syncthreads();
    for (int s = 128; s > 0; s >>= 1) { if (t < s) red[t] += red[t + s]; __syncthreads(); }
    float sumB = red[0]; __syncthreads();

    v = (t < BB) ? g_dwterm[t * EE] : 0.f;
    red[t] = v; __syncthreads();
    for (int s = 128; s > 0; s >>= 1) { if (t < s) red[t] += red[t + s]; __syncthreads(); }
    float sumB0 = red[0];

    if (t == 0) {
        out[(size_t)BB * NN * DD]     = (sumA - sumAd) / (float)(BB * (size_t)NN * (NN - 1));
        out[(size_t)BB * NN * DD + 1] = (sumB - sumB0) / (float)(BB * EE * (EE - 1));
    }
}

// ---------------- K8: w2 pass (h-split 16, gelu fused in staging) ----------------
// grid (x = dc(2) x hs(16) = 32, e=32) = 1024 blocks, 128 threads
__global__ __launch_bounds__(128) void k_w2(
    const float* __restrict__ w2, const float* __restrict__ b1) {
    int e = blockIdx.y;
    int dc = blockIdx.x & 1;
    int hs = blockIdx.x >> 1;
    int d0 = dc * 512 + threadIdx.x * 4;
    int h0 = hs * 256;

    __shared__ float4 hsm4[256];  // [hh] -> (b0,b1,b2,b3)
    for (int i = threadIdx.x; i < 4 * 256; i += 128) {
        int b = i >> 8, hh = i & 255;
        size_t hidx = (size_t)(e * 4 + b) * HH + h0 + hh;
        float v = g_h1p[0][hidx] + g_h1p[1][hidx] + g_h1p[2][hidx] + g_h1p[3][hidx] +
                  b1[e * HH + h0 + hh];
        v = v * normcdff(v);
        reinterpret_cast<float*>(hsm4)[hh * 4 + b] = v;
    }
    __syncthreads();

    float4 a0 = make_float4(0.f, 0.f, 0.f, 0.f), a1 = a0, a2 = a0, a3 = a0;
    const float4* wp = reinterpret_cast<const float4*>(
        w2 + (size_t)e * HH * DD + (size_t)h0 * DD) + (d0 >> 2);
#pragma unroll 8
    for (int hh = 0; hh < 256; hh++) {
        float4 wv = __ldcs(wp);
        wp += (DD / 4);
        float4 hv = hsm4[hh];
        a0.x += hv.x * wv.x; a0.y += hv.x * wv.y; a0.z += hv.x * wv.z; a0.w += hv.x * wv.w;
        a1.x += hv.y * wv.x; a1.y += hv.y * wv.y; a1.z += hv.y * wv.z; a1.w += hv.y * wv.w;
        a2.x += hv.z * wv.x; a2.y += hv.z * wv.y; a2.z += hv.z * wv.z; a2.w += hv.z * wv.w;
        a3.x += hv.w * wv.x; a3.y += hv.w * wv.y; a3.z += hv.w * wv.z; a3.w += hv.w * wv.w;
    }
    *reinterpret_cast<float4*>(&g_eo_part[hs][((0 * EE) + e) * DD + d0]) = a0;
    *reinterpret_cast<float4*>(&g_eo_part[hs][((1 * EE) + e) * DD + d0]) = a1;
    *reinterpret_cast<float4*>(&g_eo_part[hs][((2 * EE) + e) * DD + d0]) = a2;
    *reinterpret_cast<float4*>(&g_eo_part[hs][((3 * EE) + e) * DD + d0]) = a3;
}

__global__ __launch_bounds__(256) void k_red_eo(const float* __restrict__ b2) {
    int i = blockIdx.x * 256 + threadIdx.x;  // 131072
    int d = i & (DD - 1);
    int e = (i >> 10) & (EE - 1);
    float s = b2[e * DD + d];
#pragma unroll
    for (int p = 0; p < 16; p++) s += g_eo_part[p][i];
    g_eo[i] = s;
}

// ---------------- K10: out[b,n,d] = sum_e cw[b,n,e] * eo[b,e,d] ----------------
__global__ __launch_bounds__(256) void k_out(float* __restrict__ out) {
    int b = blockIdx.z;
    int n0 = blockIdx.y * 32;
    int d = blockIdx.x * 256 + threadIdx.x;

    __shared__ float cws[32][EE];
    for (int i = threadIdx.x; i < 32 * EE; i += 256)
        cws[i >> 5][i & 31] = g_cw[((b * NN) + (n0 + (i >> 5))) * EE + (i & 31)];
    __syncthreads();

    float acc[32];
#pragma unroll
    for (int i = 0; i < 32; i++) acc[i] = 0.f;

#pragma unroll 8
    for (int e = 0; e < EE; e++) {
        float ev = g_eo[((b * EE) + e) * DD + d];
#pragma unroll
        for (int i = 0; i < 32; i++) acc[i] += cws[i][e] * ev;
    }
#pragma unroll
    for (int i = 0; i < 32; i++)
        out[((size_t)(b * NN) + (n0 + i)) * DD + d] = acc[i];
}

// ---------------- launch ----------------
extern "C" void kernel_launch(void* const* d_in, const int* in_sizes, int n_in,
                              void* d_out, int out_size) {
    const float* x   = (const float*)d_in[0];
    const float* phi = (const float*)d_in[1];
    const float* kg  = (const float*)d_in[2];
    const float* kb  = (const float*)d_in[3];
    const float* qg  = (const float*)d_in[4];
    const float* qb  = (const float*)d_in[5];
    const float* lg  = (const float*)d_in[6];
    const float* lb  = (const float*)d_in[7];
    const float* sc  = (const float*)d_in[8];
    const float* w1  = (const float*)d_in[9];
    const float* b1  = (const float*)d_in[10];
    const float* w2  = (const float*)d_in[11];
    const float* b2  = (const float*)d_in[12];
    float* out = (float*)d_out;

    k_qnorm<<<EE, 256>>>(phi, qg, qb, lg, lb, sc);
    k_logits<<<dim3(32, 4), 256>>>(x, kg, kb);
    k_dstats<<<BB * EE, 256>>>();
    k_slots<<<dim3(16, 4, 4), 256>>>(x);      // 4th launch -> ncu capture slot
    k_w1<<<dim3(8, 4, 32), 128>>>(w1);
    k_combine<<<64, 256>>>();
    k_scalars<<<1, 256>>>(out);
    k_w2<<<dim3(32, 32), 128>>>(w2, b1);
    k_red_eo<<<512, 256>>>(b2);
    k_out<<<dim3(4, 32, 4), 256>>>(out);
}